// round 1
// baseline (speedup 1.0000x reference)
#include <cuda_runtime.h>

// ---------------------------------------------------------------------------
// Problem: out[M,N] = segment_mean(gather(cf, member_idx), segment_ids) @ W + b
//   cf: [num_chunks, K] fp32, member_idx: [Mm] int32, segment_ids: [Mm] int32 (sorted)
//   W: [K, N] fp32, b: [N] fp32.   M = num_cells (derived from out_size / N)
// ---------------------------------------------------------------------------

#define MAX_ROWS 65536   // padded M capacity (multiple of BM)
#define MAX_K    256

// Zero-initialized scratch for cell embeddings (means). Rows >= M never
// written -> stay zero, so GEMM A-loads need no bounds checks.
__device__ float g_cell[(size_t)MAX_ROWS * MAX_K];

// ---------------------------------------------------------------------------
// f32x2 packed-math helpers (Blackwell FFMA2 — PTX-only, doubles fp32 tput)
// ---------------------------------------------------------------------------
__device__ __forceinline__ void fma2(unsigned long long& acc,
                                     unsigned long long a,
                                     unsigned long long b) {
    asm("fma.rn.f32x2 %0, %1, %2, %0;" : "+l"(acc) : "l"(a), "l"(b));
}
__device__ __forceinline__ unsigned long long dup2(float x) {
    unsigned long long r;
    asm("mov.b64 %0, {%1, %1};" : "=l"(r) : "f"(x));
    return r;
}
__device__ __forceinline__ unsigned long long pack2(float x, float y) {
    unsigned long long r;
    asm("mov.b64 %0, {%1, %2};" : "=l"(r) : "f"(x), "f"(y));
    return r;
}
__device__ __forceinline__ float2 unpack2(unsigned long long v) {
    float2 r;
    asm("mov.b64 {%0, %1}, %2;" : "=f"(r.x), "=f"(r.y) : "l"(v));
    return r;
}

// ---------------------------------------------------------------------------
// Kernel 1: segment mean. One block per cell. segment_ids sorted -> binary
// search gives the contiguous member range. blockDim = K/4; each thread owns
// one float4 of the embedding dimension (fully coalesced 1KB row reads).
// ---------------------------------------------------------------------------
__device__ __forceinline__ int lower_bound_i(const int* __restrict__ a, int n, int key) {
    int lo = 0, hi = n;
    while (lo < hi) {
        int mid = (lo + hi) >> 1;
        if (a[mid] < key) lo = mid + 1; else hi = mid;
    }
    return lo;
}

__global__ void mean_kernel(const float4* __restrict__ cf4,
                            const int* __restrict__ midx,
                            const int* __restrict__ seg,
                            int num_members, int K4) {
    const int c = blockIdx.x;
    const int tid = threadIdx.x;
    __shared__ int s_range[2];
    __shared__ int s_idx[64];

    if (tid == 0) s_range[0] = lower_bound_i(seg, num_members, c);
    if (tid == 1 || blockDim.x == 1) s_range[1] = lower_bound_i(seg, num_members, c + 1);
    __syncthreads();
    const int start = s_range[0];
    const int end   = s_range[1];

    float4 a0 = make_float4(0.f, 0.f, 0.f, 0.f);
    float4 a1 = make_float4(0.f, 0.f, 0.f, 0.f);

    for (int j0 = start; j0 < end; j0 += 64) {
        __syncthreads();
        int j = j0 + tid;
        if (tid < 64 && j < end) s_idx[tid] = midx[j] * K4;
        __syncthreads();
        int n = min(64, end - j0);
        int u = 0;
        for (; u + 2 <= n; u += 2) {
            float4 v0 = cf4[(size_t)s_idx[u]     + tid];
            float4 v1 = cf4[(size_t)s_idx[u + 1] + tid];
            a0.x += v0.x; a0.y += v0.y; a0.z += v0.z; a0.w += v0.w;
            a1.x += v1.x; a1.y += v1.y; a1.z += v1.z; a1.w += v1.w;
        }
        if (u < n) {
            float4 v0 = cf4[(size_t)s_idx[u] + tid];
            a0.x += v0.x; a0.y += v0.y; a0.z += v0.z; a0.w += v0.w;
        }
    }

    float cnt = (float)(end - start);
    float inv = 1.0f / fmaxf(cnt, 1.0f);
    float4 r;
    r.x = (a0.x + a1.x) * inv;
    r.y = (a0.y + a1.y) * inv;
    r.z = (a0.z + a1.z) * inv;
    r.w = (a0.w + a1.w) * inv;
    ((float4*)g_cell)[(size_t)c * K4 + tid] = r;
}

// ---------------------------------------------------------------------------
// Kernel 2: SGEMM  C[M,N] = A[M,K] @ W[K,N] + b   with f32x2 packed FMAs.
// 128x128 block tile, BK=8, 256 threads, 8x8 per-thread microtile packed as
// 8x4 f32x2 accumulators (column pairs).
// ---------------------------------------------------------------------------
#define BM 128
#define BN 128
#define BK 8
#define BMP (BM + 4)   // padded As row to kill STS bank conflicts

__global__ __launch_bounds__(256, 2)
void gemm_kernel(const float* __restrict__ W,
                 const float* __restrict__ bias,
                 float* __restrict__ C,
                 int M, int N, int K) {
    __shared__ float As[BK][BMP];
    __shared__ float Bs[BK][BN];

    const int tid = threadIdx.x;
    const int bm = blockIdx.x * BM;
    const int bn = blockIdx.y * BN;
    const float* __restrict__ A = g_cell;

    // global-load assignments
    const int arow = tid >> 1;          // 0..127
    const int acol = (tid & 1) * 4;     // 0 or 4
    const int brow = tid >> 5;          // 0..7
    const int bcol = (tid & 31) * 4;    // 0..124

    // microtile position
    const int tm = (tid >> 4) * 8;      // 0..120
    const int tn = (tid & 15) * 8;      // 0..120

    unsigned long long acc[8][4];
#pragma unroll
    for (int i = 0; i < 8; i++)
#pragma unroll
        for (int j = 0; j < 4; j++) acc[i][j] = 0ull;

    for (int kt = 0; kt < K; kt += BK) {
        float4 av = *(const float4*)&A[(size_t)(bm + arow) * K + kt + acol];
        float4 bv = *(const float4*)&W[(size_t)(kt + brow) * N + bn + bcol];
        __syncthreads();
        As[acol + 0][arow] = av.x;
        As[acol + 1][arow] = av.y;
        As[acol + 2][arow] = av.z;
        As[acol + 3][arow] = av.w;
        *(float4*)&Bs[brow][bcol] = bv;
        __syncthreads();

#pragma unroll
        for (int k = 0; k < BK; k++) {
            float4 aq0 = *(const float4*)&As[k][tm];
            float4 aq1 = *(const float4*)&As[k][tm + 4];
            float4 bq0 = *(const float4*)&Bs[k][tn];
            float4 bq1 = *(const float4*)&Bs[k][tn + 4];

            unsigned long long b2[4];
            b2[0] = pack2(bq0.x, bq0.y);
            b2[1] = pack2(bq0.z, bq0.w);
            b2[2] = pack2(bq1.x, bq1.y);
            b2[3] = pack2(bq1.z, bq1.w);

            float a[8] = {aq0.x, aq0.y, aq0.z, aq0.w, aq1.x, aq1.y, aq1.z, aq1.w};
#pragma unroll
            for (int i = 0; i < 8; i++) {
                unsigned long long a2 = dup2(a[i]);
                fma2(acc[i][0], a2, b2[0]);
                fma2(acc[i][1], a2, b2[1]);
                fma2(acc[i][2], a2, b2[2]);
                fma2(acc[i][3], a2, b2[3]);
            }
        }
    }

    // epilogue: add bias, store (guard rows >= M)
    float2 bb[4];
#pragma unroll
    for (int j = 0; j < 4; j++)
        bb[j] = *(const float2*)&bias[bn + tn + 2 * j];

#pragma unroll
    for (int i = 0; i < 8; i++) {
        int row = bm + tm + i;
        if (row < M) {
#pragma unroll
            for (int j = 0; j < 4; j++) {
                float2 v = unpack2(acc[i][j]);
                float2 o;
                o.x = v.x + bb[j].x;
                o.y = v.y + bb[j].y;
                *(float2*)&C[(size_t)row * N + bn + tn + 2 * j] = o;
            }
        }
    }
}

// ---------------------------------------------------------------------------
// Launch. Inputs (metadata order): chunk_features, member_idx, segment_ids,
// num_cells (device scalar, unused — derived from out_size), W, b.
// ---------------------------------------------------------------------------
extern "C" void kernel_launch(void* const* d_in, const int* in_sizes, int n_in,
                              void* d_out, int out_size) {
    const float* cf  = (const float*)d_in[0];
    const int* midx  = (const int*)d_in[1];
    const int* seg   = (const int*)d_in[2];
    const float* W   = (const float*)d_in[4];
    const float* bias = (const float*)d_in[5];
    float* out = (float*)d_out;

    const int N = in_sizes[5];              // output_dim (512)
    const int K = in_sizes[4] / N;          // input_dim  (256)
    const int M = out_size / N;             // num_cells  (50000)
    const int num_members = in_sizes[1];    // 400000
    const int K4 = K / 4;

    mean_kernel<<<M, K4>>>((const float4*)cf, midx, seg, num_members, K4);

    dim3 grid((M + BM - 1) / BM, N / BN);
    gemm_kernel<<<grid, 256>>>(W, bias, out, M, N, K);
}

// round 3
// speedup vs baseline: 2.0908x; 2.0908x over previous
#include <cuda_runtime.h>
#include <cuda_bf16.h>
#include <cstdint>

// ---------------------------------------------------------------------------
// out[M,N] = segment_mean(gather(cf, member_idx), segment_ids) @ W + b
// starts[] pass -> mean kernel (emits bf16 hi/lo split A) -> W prepack
// (transpose + hi/lo) -> mma.sync bf16 GEMM, 3-term split, fp32 accumulate.
// (tcgen05 is unusable: harness compiles through compute_103 PTX, which
//  rejects all sm_103a-only instructions. mma.sync/ldmatrix/cp.async are
//  baseline sm_80 features and compile fine.)
// ---------------------------------------------------------------------------

#define MAX_ROWS_PAD 65664          // multiple of 128, >= padded M
#define AK 256                      // K (input_dim) capacity

// Zero-initialized scratch. Rows >= M are never written -> stay zero, so the
// GEMM needs no A-row guards.
__device__ __nv_bfloat16 g_a_hi[(size_t)MAX_ROWS_PAD * AK];
__device__ __nv_bfloat16 g_a_lo[(size_t)MAX_ROWS_PAD * AK];
__device__ __nv_bfloat16 g_b_hi[1024 * 512];   // [N][K] (W transposed)
__device__ __nv_bfloat16 g_b_lo[1024 * 512];
__device__ int g_starts[65600];

// ---------------------------------------------------------------------------
// PTX helpers (all baseline sm_80/sm_90 features — safe on compute_103)
// ---------------------------------------------------------------------------
__device__ __forceinline__ uint32_t smem_u32(const void* p) {
    uint32_t a;
    asm("{ .reg .u64 t; cvta.to.shared.u64 t, %1; cvt.u32.u64 %0, t; }"
        : "=r"(a) : "l"(p));
    return a;
}

#define CP16(dst, src) \
    asm volatile("cp.async.cg.shared.global [%0], [%1], 16;" \
                 :: "r"(dst), "l"(src) : "memory")
#define CP_COMMIT() asm volatile("cp.async.commit_group;" ::: "memory")
#define CP_WAIT0()  asm volatile("cp.async.wait_group 0;" ::: "memory")

#define LDM4(r, a) \
    asm volatile("ldmatrix.sync.aligned.m8n8.x4.shared.b16 {%0,%1,%2,%3}, [%4];" \
                 : "=r"((r)[0]), "=r"((r)[1]), "=r"((r)[2]), "=r"((r)[3]) \
                 : "r"(a))

#define MMA_BF16(d, a, b) \
    asm volatile("mma.sync.aligned.m16n8k16.row.col.f32.bf16.bf16.f32 " \
                 "{%0,%1,%2,%3}, {%4,%5,%6,%7}, {%8,%9}, {%0,%1,%2,%3};" \
                 : "+f"((d)[0]), "+f"((d)[1]), "+f"((d)[2]), "+f"((d)[3]) \
                 : "r"((a)[0]), "r"((a)[1]), "r"((a)[2]), "r"((a)[3]), \
                   "r"((b)[0]), "r"((b)[1]))

// ---------------------------------------------------------------------------
// Kernel 0: segment starts (removes per-cell binary searches)
// ---------------------------------------------------------------------------
__global__ void starts_kernel(const int* __restrict__ seg, int num_members, int num_cells) {
    int i = blockIdx.x * blockDim.x + threadIdx.x;
    if (i > num_members) return;
    int cur  = (i < num_members) ? seg[i] : num_cells;
    int prev = (i > 0) ? seg[i - 1] : -1;
    for (int c = prev + 1; c <= cur; c++) g_starts[c] = i;
}

// ---------------------------------------------------------------------------
// Kernel 1: segment mean + bf16 hi/lo split. One block (64 thr) per cell;
// thread t owns float4 chunk t of the 256-dim embedding.
// ---------------------------------------------------------------------------
__global__ void mean_kernel(const float4* __restrict__ cf4,
                            const int* __restrict__ midx,
                            int K4) {
    const int c = blockIdx.x;
    const int tid = threadIdx.x;
    const int start = __ldg(&g_starts[c]);
    const int end   = __ldg(&g_starts[c + 1]);
    __shared__ int s_idx[64];

    float4 a0 = make_float4(0.f, 0.f, 0.f, 0.f);
    float4 a1 = make_float4(0.f, 0.f, 0.f, 0.f);

    for (int j0 = start; j0 < end; j0 += 64) {
        __syncthreads();
        if (j0 + tid < end) s_idx[tid] = midx[j0 + tid] * K4;
        __syncthreads();
        int n = min(64, end - j0);
        int u = 0;
        for (; u + 2 <= n; u += 2) {
            float4 v0 = cf4[(size_t)s_idx[u]     + tid];
            float4 v1 = cf4[(size_t)s_idx[u + 1] + tid];
            a0.x += v0.x; a0.y += v0.y; a0.z += v0.z; a0.w += v0.w;
            a1.x += v1.x; a1.y += v1.y; a1.z += v1.z; a1.w += v1.w;
        }
        if (u < n) {
            float4 v0 = cf4[(size_t)s_idx[u] + tid];
            a0.x += v0.x; a0.y += v0.y; a0.z += v0.z; a0.w += v0.w;
        }
    }

    float inv = 1.0f / fmaxf((float)(end - start), 1.0f);
    float v[4];
    v[0] = (a0.x + a1.x) * inv;
    v[1] = (a0.y + a1.y) * inv;
    v[2] = (a0.z + a1.z) * inv;
    v[3] = (a0.w + a1.w) * inv;

    uint32_t hp[2], lp[2];
#pragma unroll
    for (int g = 0; g < 2; g++) {
        __nv_bfloat16 h0 = __float2bfloat16(v[2 * g]);
        __nv_bfloat16 h1 = __float2bfloat16(v[2 * g + 1]);
        __nv_bfloat16 l0 = __float2bfloat16(v[2 * g]     - __bfloat162float(h0));
        __nv_bfloat16 l1 = __float2bfloat16(v[2 * g + 1] - __bfloat162float(h1));
        hp[g] = (uint32_t)__bfloat16_as_ushort(h0) | ((uint32_t)__bfloat16_as_ushort(h1) << 16);
        lp[g] = (uint32_t)__bfloat16_as_ushort(l0) | ((uint32_t)__bfloat16_as_ushort(l1) << 16);
    }
    size_t o = (size_t)c * K4 + tid;   // uint2 units (4 bf16 = 8B)
    ((uint2*)g_a_hi)[o] = make_uint2(hp[0], hp[1]);
    ((uint2*)g_a_lo)[o] = make_uint2(lp[0], lp[1]);
}

// ---------------------------------------------------------------------------
// Kernel 2: W prepack -> [N][K] bf16 hi/lo (transposed: B^T row-major, which
// is exactly the col-major B layout mma.sync wants via ldmatrix)
// ---------------------------------------------------------------------------
__global__ void prepw_kernel(const float* __restrict__ W, int K, int N) {
    int idx = blockIdx.x * blockDim.x + threadIdx.x;
    if (idx >= K * N) return;
    int n = idx / K, k = idx - n * K;
    float w = W[(size_t)k * N + n];
    __nv_bfloat16 h = __float2bfloat16(w);
    __nv_bfloat16 l = __float2bfloat16(w - __bfloat162float(h));
    g_b_hi[(size_t)n * K + k] = h;
    g_b_lo[(size_t)n * K + k] = l;
}

// ---------------------------------------------------------------------------
// Kernel 3: bf16 mma.sync GEMM, 3-term split:
//   D = Ah@Bh^T + Ah@Bl^T + Al@Bh^T   (fp32 accumulate)
// CTA tile 128x128, BK=32, 256 thr = 8 warps (4 M x 2 N), warp tile 32x64.
// Double-buffered cp.async. Smem rows are 64B (32 bf16) with XOR-swizzled
// 16B chunks: off(r,c) = r*64 + ((c ^ ((r>>1)&3))<<4)  -> conflict-free
// ldmatrix (8 rows hit 8 distinct 16B bank-quads).
// Stage layout: Ah[8K] Al[8K] Bh[8K] Bl[8K] = 32KB; 2 stages = 64KB.
// ---------------------------------------------------------------------------
#define STAGE_BYTES 32768u
#define SEC_BYTES   8192u

__global__ __launch_bounds__(256, 1)
void gemm_mma_kernel(const float* __restrict__ bias, float* __restrict__ C,
                     int M, int N, int K) {
    extern __shared__ char smem[];
    const uint32_t sb = smem_u32(smem);
    const int tid  = threadIdx.x;
    const int wid  = tid >> 5, lane = tid & 31;
    const int wm   = wid & 3;            // warp row   (0..3)  -> 32 rows
    const int wn   = wid >> 2;           // warp col   (0..1)  -> 64 cols
    const int bm   = blockIdx.x * 128, bn = blockIdx.y * 128;
    const size_t rowb = (size_t)K * 2;   // bytes per gmem row

    const char* pAh = (const char*)g_a_hi + (size_t)bm * rowb;
    const char* pAl = (const char*)g_a_lo + (size_t)bm * rowb;
    const char* pBh = (const char*)g_b_hi + (size_t)bn * rowb;
    const char* pBl = (const char*)g_b_lo + (size_t)bn * rowb;

    // this thread's two (row, chunk) load slots per section
    const int li0 = tid * 2, li1 = tid * 2 + 1;
    const int lr0 = li0 >> 2, lc0 = li0 & 3;
    const int lr1 = li1 >> 2, lc1 = li1 & 3;
    const uint32_t ld0 = (uint32_t)(lr0 * 64 + (((lc0 ^ ((lr0 >> 1) & 3))) << 4));
    const uint32_t ld1 = (uint32_t)(lr1 * 64 + (((lc1 ^ ((lr1 >> 1) & 3))) << 4));

    float acc[2][8][4];
#pragma unroll
    for (int g = 0; g < 2; g++)
#pragma unroll
        for (int n = 0; n < 8; n++)
#pragma unroll
            for (int j = 0; j < 4; j++) acc[g][n][j] = 0.f;

    // precompute ldmatrix addresses (stage-relative)
    // A: group g in {0,1}: row = wm*32 + g*16 + (lane&15), chunk = s*2 + (lane>>4)
    const int a_r = (lane & 15);
    const int a_cadd = (lane >> 4);
    // B: group h in {0..3}: row = wn*64 + h*16 + (lane&7) + ((lane>>4)<<3),
    //    chunk = s*2 + ((lane>>3)&1)
    const int b_r = (lane & 7) + ((lane >> 4) << 3);
    const int b_cadd = ((lane >> 3) & 1);

    const int nit = K >> 5;              // 8 for K=256

    // prologue: load stage 0
    {
        const uint32_t sbase = sb;
#pragma unroll
        for (int s = 0; s < 4; s++) {
            const char* gp = (s == 0) ? pAh : (s == 1) ? pAl : (s == 2) ? pBh : pBl;
            CP16(sbase + s * SEC_BYTES + ld0, gp + (size_t)lr0 * rowb + lc0 * 16);
            CP16(sbase + s * SEC_BYTES + ld1, gp + (size_t)lr1 * rowb + lc1 * 16);
        }
        CP_COMMIT();
    }

    for (int it = 0; it < nit; it++) {
        const uint32_t stg = sb + (uint32_t)(it & 1) * STAGE_BYTES;
        CP_WAIT0();
        __syncthreads();

        if (it + 1 < nit) {
            const uint32_t sbase = sb + (uint32_t)((it + 1) & 1) * STAGE_BYTES;
            const size_t kt2 = (size_t)(it + 1) * 64;   // 32 bf16 = 64 B
#pragma unroll
            for (int s = 0; s < 4; s++) {
                const char* gp = (s == 0) ? pAh : (s == 1) ? pAl : (s == 2) ? pBh : pBl;
                CP16(sbase + s * SEC_BYTES + ld0, gp + (size_t)lr0 * rowb + kt2 + lc0 * 16);
                CP16(sbase + s * SEC_BYTES + ld1, gp + (size_t)lr1 * rowb + kt2 + lc1 * 16);
            }
            CP_COMMIT();
        }

        // compute: two k16 steps on this stage
#pragma unroll
        for (int s = 0; s < 2; s++) {
            uint32_t ah[2][4], al[2][4];
#pragma unroll
            for (int g = 0; g < 2; g++) {
                int row = wm * 32 + g * 16 + a_r;
                int ch  = s * 2 + a_cadd;
                uint32_t addr = stg + row * 64 + (((ch ^ ((row >> 1) & 3))) << 4);
                LDM4(ah[g], addr);
                LDM4(al[g], addr + SEC_BYTES);
            }
#pragma unroll
            for (int h = 0; h < 4; h++) {
                int row = wn * 64 + h * 16 + b_r;
                int ch  = s * 2 + b_cadd;
                uint32_t addr = stg + 2 * SEC_BYTES + row * 64 +
                                (((ch ^ ((row >> 1) & 3))) << 4);
                uint32_t rbh[4], rbl[4];
                LDM4(rbh, addr);
                LDM4(rbl, addr + SEC_BYTES);
                uint32_t bh0[2] = {rbh[0], rbh[1]}, bh1[2] = {rbh[2], rbh[3]};
                uint32_t bl0[2] = {rbl[0], rbl[1]}, bl1[2] = {rbl[2], rbl[3]};
#pragma unroll
                for (int g = 0; g < 2; g++) {
                    MMA_BF16(acc[g][h * 2],     ah[g], bh0);
                    MMA_BF16(acc[g][h * 2],     al[g], bh0);
                    MMA_BF16(acc[g][h * 2],     ah[g], bl0);
                    MMA_BF16(acc[g][h * 2 + 1], ah[g], bh1);
                    MMA_BF16(acc[g][h * 2 + 1], al[g], bh1);
                    MMA_BF16(acc[g][h * 2 + 1], ah[g], bl1);
                }
            }
        }
        __syncthreads();
    }

    // epilogue: bias add + store (fragment layout: lane>>2 = row-in-8,
    // (lane&3)*2 = col pair; c2,c3 are row+8)
#pragma unroll
    for (int g = 0; g < 2; g++) {
        int row0 = bm + wm * 32 + g * 16 + (lane >> 2);
        int row1 = row0 + 8;
#pragma unroll
        for (int n = 0; n < 8; n++) {
            int col = bn + wn * 64 + n * 8 + (lane & 3) * 2;
            float2 bb = *(const float2*)&bias[col];
            if (row0 < M) {
                float2 o = make_float2(acc[g][n][0] + bb.x, acc[g][n][1] + bb.y);
                *(float2*)&C[(size_t)row0 * N + col] = o;
            }
            if (row1 < M) {
                float2 o = make_float2(acc[g][n][2] + bb.x, acc[g][n][3] + bb.y);
                *(float2*)&C[(size_t)row1 * N + col] = o;
            }
        }
    }
}

// ---------------------------------------------------------------------------
// Launch
// ---------------------------------------------------------------------------
extern "C" void kernel_launch(void* const* d_in, const int* in_sizes, int n_in,
                              void* d_out, int out_size) {
    const float* cf   = (const float*)d_in[0];
    const int* midx   = (const int*)d_in[1];
    const int* seg    = (const int*)d_in[2];
    const float* W    = (const float*)d_in[4];
    const float* bias = (const float*)d_in[5];
    float* out = (float*)d_out;

    const int N = in_sizes[5];           // 512
    const int K = in_sizes[4] / N;       // 256
    const int M = out_size / N;          // 50000
    const int num_members = in_sizes[1]; // 400000
    const int K4 = K / 4;

    cudaFuncSetAttribute(gemm_mma_kernel,
                         cudaFuncAttributeMaxDynamicSharedMemorySize,
                         (int)(2 * STAGE_BYTES));

    starts_kernel<<<(num_members + 256) / 256, 256>>>(seg, num_members, M);
    prepw_kernel<<<(K * N + 255) / 256, 256>>>(W, K, N);
    mean_kernel<<<M, K4>>>((const float4*)cf, midx, K4);

    dim3 grid((M + 127) / 128, N / 128);
    gemm_mma_kernel<<<grid, 256, 2 * STAGE_BYTES>>>(bias, out, M, N, K);
}

// round 4
// speedup vs baseline: 2.1298x; 1.0187x over previous
#include <cuda_runtime.h>
#include <cuda_bf16.h>
#include <cstdint>

// ---------------------------------------------------------------------------
// out[M,N] = segment_mean(gather(cf, member_idx), segment_ids) @ W + b
// starts[] pass -> mean kernel (emits bf16 hi/lo split A) -> W prepack
// (transpose + hi/lo) -> mma.sync bf16 GEMM, 3-term split, fp32 accumulate.
// R4: 3-stage cp.async pipeline + MMA pass reorder (kill acc RAW chains),
//     sync-free mean kernel.
// ---------------------------------------------------------------------------

#define MAX_ROWS_PAD 65664          // multiple of 128, >= padded M
#define AK 256                      // K (input_dim) capacity

// Zero-initialized scratch. Rows >= M are never written -> stay zero, so the
// GEMM needs no A-row guards.
__device__ __nv_bfloat16 g_a_hi[(size_t)MAX_ROWS_PAD * AK];
__device__ __nv_bfloat16 g_a_lo[(size_t)MAX_ROWS_PAD * AK];
__device__ __nv_bfloat16 g_b_hi[1024 * 512];   // [N][K] (W transposed)
__device__ __nv_bfloat16 g_b_lo[1024 * 512];
__device__ int g_starts[65600];

// ---------------------------------------------------------------------------
// PTX helpers (baseline sm_80 features — safe through compute_103 PTX)
// ---------------------------------------------------------------------------
__device__ __forceinline__ uint32_t smem_u32(const void* p) {
    uint32_t a;
    asm("{ .reg .u64 t; cvta.to.shared.u64 t, %1; cvt.u32.u64 %0, t; }"
        : "=r"(a) : "l"(p));
    return a;
}

#define CP16(dst, src) \
    asm volatile("cp.async.cg.shared.global [%0], [%1], 16;" \
                 :: "r"(dst), "l"(src) : "memory")
#define CP_COMMIT() asm volatile("cp.async.commit_group;" ::: "memory")
#define CP_WAIT1()  asm volatile("cp.async.wait_group 1;" ::: "memory")

#define LDM4(r, a) \
    asm volatile("ldmatrix.sync.aligned.m8n8.x4.shared.b16 {%0,%1,%2,%3}, [%4];" \
                 : "=r"((r)[0]), "=r"((r)[1]), "=r"((r)[2]), "=r"((r)[3]) \
                 : "r"(a))

#define MMA_BF16(d, a, b0, b1) \
    asm volatile("mma.sync.aligned.m16n8k16.row.col.f32.bf16.bf16.f32 " \
                 "{%0,%1,%2,%3}, {%4,%5,%6,%7}, {%8,%9}, {%0,%1,%2,%3};" \
                 : "+f"((d)[0]), "+f"((d)[1]), "+f"((d)[2]), "+f"((d)[3]) \
                 : "r"((a)[0]), "r"((a)[1]), "r"((a)[2]), "r"((a)[3]), \
                   "r"(b0), "r"(b1))

// ---------------------------------------------------------------------------
// Kernel 0: segment starts
// ---------------------------------------------------------------------------
__global__ void starts_kernel(const int* __restrict__ seg, int num_members, int num_cells) {
    int i = blockIdx.x * blockDim.x + threadIdx.x;
    if (i > num_members) return;
    int cur  = (i < num_members) ? seg[i] : num_cells;
    int prev = (i > 0) ? seg[i - 1] : -1;
    for (int c = prev + 1; c <= cur; c++) g_starts[c] = i;
}

// ---------------------------------------------------------------------------
// Kernel 1: segment mean + bf16 hi/lo split. One block (64 thr) per cell;
// thread t owns float4 chunk t. Index loads are uniform across the block
// (broadcast), no smem staging, no __syncthreads.
// ---------------------------------------------------------------------------
__global__ void mean_kernel(const float4* __restrict__ cf4,
                            const int* __restrict__ midx,
                            int K4) {
    const int c = blockIdx.x;
    const int tid = threadIdx.x;
    const int start = __ldg(&g_starts[c]);
    const int end   = __ldg(&g_starts[c + 1]);

    float4 a0 = make_float4(0.f, 0.f, 0.f, 0.f);
    float4 a1 = make_float4(0.f, 0.f, 0.f, 0.f);

    int j = start;
    for (; j + 2 <= end; j += 2) {
        int i0 = __ldg(&midx[j])     * K4;
        int i1 = __ldg(&midx[j + 1]) * K4;
        float4 v0 = cf4[(size_t)i0 + tid];
        float4 v1 = cf4[(size_t)i1 + tid];
        a0.x += v0.x; a0.y += v0.y; a0.z += v0.z; a0.w += v0.w;
        a1.x += v1.x; a1.y += v1.y; a1.z += v1.z; a1.w += v1.w;
    }
    if (j < end) {
        int i0 = __ldg(&midx[j]) * K4;
        float4 v0 = cf4[(size_t)i0 + tid];
        a0.x += v0.x; a0.y += v0.y; a0.z += v0.z; a0.w += v0.w;
    }

    float inv = 1.0f / fmaxf((float)(end - start), 1.0f);
    float v[4];
    v[0] = (a0.x + a1.x) * inv;
    v[1] = (a0.y + a1.y) * inv;
    v[2] = (a0.z + a1.z) * inv;
    v[3] = (a0.w + a1.w) * inv;

    uint32_t hp[2], lp[2];
#pragma unroll
    for (int g = 0; g < 2; g++) {
        __nv_bfloat16 h0 = __float2bfloat16(v[2 * g]);
        __nv_bfloat16 h1 = __float2bfloat16(v[2 * g + 1]);
        __nv_bfloat16 l0 = __float2bfloat16(v[2 * g]     - __bfloat162float(h0));
        __nv_bfloat16 l1 = __float2bfloat16(v[2 * g + 1] - __bfloat162float(h1));
        hp[g] = (uint32_t)__bfloat16_as_ushort(h0) | ((uint32_t)__bfloat16_as_ushort(h1) << 16);
        lp[g] = (uint32_t)__bfloat16_as_ushort(l0) | ((uint32_t)__bfloat16_as_ushort(l1) << 16);
    }
    size_t o = (size_t)c * K4 + tid;   // uint2 units (4 bf16 = 8B)
    ((uint2*)g_a_hi)[o] = make_uint2(hp[0], hp[1]);
    ((uint2*)g_a_lo)[o] = make_uint2(lp[0], lp[1]);
}

// ---------------------------------------------------------------------------
// Kernel 2: W prepack -> [N][K] bf16 hi/lo
// ---------------------------------------------------------------------------
__global__ void prepw_kernel(const float* __restrict__ W, int K, int N) {
    int idx = blockIdx.x * blockDim.x + threadIdx.x;
    if (idx >= K * N) return;
    int n = idx / K, k = idx - n * K;
    float w = W[(size_t)k * N + n];
    __nv_bfloat16 h = __float2bfloat16(w);
    __nv_bfloat16 l = __float2bfloat16(w - __bfloat162float(h));
    g_b_hi[(size_t)n * K + k] = h;
    g_b_lo[(size_t)n * K + k] = l;
}

// ---------------------------------------------------------------------------
// Kernel 3: bf16 mma.sync GEMM, 3-term split, 3-stage cp.async pipeline.
// CTA tile 128x128, BK=32, 256 thr = 8 warps (4 M x 2 N), warp tile 32x64.
// Smem rows 64B (32 bf16), XOR-swizzled 16B chunks for conflict-free ldmatrix.
// Stage layout: Ah[8K] Al[8K] Bh[8K] Bl[8K] = 32KB; 3 stages = 96KB.
// MMA ordering: per k16-step, per h-pair, three passes (hh / lh / hl) of 8
// independent MMAs each -> same-acc reuse distance 8 (covers HMMA latency).
// ---------------------------------------------------------------------------
#define STAGE_BYTES 32768u
#define SEC_BYTES   8192u
#define NSTAGE      3

__global__ __launch_bounds__(256, 1)
void gemm_mma_kernel(const float* __restrict__ bias, float* __restrict__ C,
                     int M, int N, int K) {
    extern __shared__ char smem[];
    const uint32_t sb = smem_u32(smem);
    const int tid  = threadIdx.x;
    const int wid  = tid >> 5, lane = tid & 31;
    const int wm   = wid & 3;            // warp row (0..3) -> 32 rows
    const int wn   = wid >> 2;           // warp col (0..1) -> 64 cols
    const int bm   = blockIdx.x * 128, bn = blockIdx.y * 128;
    const size_t rowb = (size_t)K * 2;   // bytes per gmem row

    const char* pAh = (const char*)g_a_hi + (size_t)bm * rowb;
    const char* pAl = (const char*)g_a_lo + (size_t)bm * rowb;
    const char* pBh = (const char*)g_b_hi + (size_t)bn * rowb;
    const char* pBl = (const char*)g_b_lo + (size_t)bn * rowb;

    // this thread's two (row, chunk) load slots per section
    const int li0 = tid * 2, li1 = tid * 2 + 1;
    const int lr0 = li0 >> 2, lc0 = li0 & 3;
    const int lr1 = li1 >> 2, lc1 = li1 & 3;
    const uint32_t ld0 = (uint32_t)(lr0 * 64 + (((lc0 ^ ((lr0 >> 1) & 3))) << 4));
    const uint32_t ld1 = (uint32_t)(lr1 * 64 + (((lc1 ^ ((lr1 >> 1) & 3))) << 4));

    float acc[2][8][4];
#pragma unroll
    for (int g = 0; g < 2; g++)
#pragma unroll
        for (int n = 0; n < 8; n++)
#pragma unroll
            for (int j = 0; j < 4; j++) acc[g][n][j] = 0.f;

    // ldmatrix lane addressing
    const int a_r = (lane & 15);
    const int a_cadd = (lane >> 4);
    const int b_r = (lane & 7) + ((lane >> 4) << 3);
    const int b_cadd = ((lane >> 3) & 1);

    const int nit = K >> 5;              // 8 for K=256

    // prologue: load stages 0 and 1
#pragma unroll
    for (int pre = 0; pre < 2; pre++) {
        const uint32_t sbase = sb + (uint32_t)pre * STAGE_BYTES;
        const size_t kt2 = (size_t)pre * 64;
#pragma unroll
        for (int s = 0; s < 4; s++) {
            const char* gp = (s == 0) ? pAh : (s == 1) ? pAl : (s == 2) ? pBh : pBl;
            CP16(sbase + s * SEC_BYTES + ld0, gp + (size_t)lr0 * rowb + kt2 + lc0 * 16);
            CP16(sbase + s * SEC_BYTES + ld1, gp + (size_t)lr1 * rowb + kt2 + lc1 * 16);
        }
        CP_COMMIT();
    }

    for (int it = 0; it < nit; it++) {
        const uint32_t stg = sb + (uint32_t)(it % NSTAGE) * STAGE_BYTES;
        CP_WAIT1();              // stage `it` complete (1 newer group may fly)
        __syncthreads();         // all warps done with stage it-1's compute

        if (it + 2 < nit) {      // prefetch stage it+2 into slot (it+2)%3
            const uint32_t sbase = sb + (uint32_t)((it + 2) % NSTAGE) * STAGE_BYTES;
            const size_t kt2 = (size_t)(it + 2) * 64;
#pragma unroll
            for (int s = 0; s < 4; s++) {
                const char* gp = (s == 0) ? pAh : (s == 1) ? pAl : (s == 2) ? pBh : pBl;
                CP16(sbase + s * SEC_BYTES + ld0, gp + (size_t)lr0 * rowb + kt2 + lc0 * 16);
                CP16(sbase + s * SEC_BYTES + ld1, gp + (size_t)lr1 * rowb + kt2 + lc1 * 16);
            }
            CP_COMMIT();
        } else {
            CP_COMMIT();         // keep group count in lockstep for WAIT1
        }

        // compute: two k16 steps on this stage
#pragma unroll
        for (int s = 0; s < 2; s++) {
            uint32_t ah[2][4], al[2][4];
#pragma unroll
            for (int g = 0; g < 2; g++) {
                int row = wm * 32 + g * 16 + a_r;
                int ch  = s * 2 + a_cadd;
                uint32_t addr = stg + row * 64 + (((ch ^ ((row >> 1) & 3))) << 4);
                LDM4(ah[g], addr);
                LDM4(al[g], addr + SEC_BYTES);
            }
#pragma unroll
            for (int hp = 0; hp < 2; hp++) {
                uint32_t bh[2][4], bl[2][4];
#pragma unroll
                for (int hh = 0; hh < 2; hh++) {
                    int h = hp * 2 + hh;
                    int row = wn * 64 + h * 16 + b_r;
                    int ch  = s * 2 + b_cadd;
                    uint32_t addr = stg + 2 * SEC_BYTES + row * 64 +
                                    (((ch ^ ((row >> 1) & 3))) << 4);
                    LDM4(bh[hh], addr);
                    LDM4(bl[hh], addr + SEC_BYTES);
                }
                // pass 1: Ah x Bh  (8 independent MMAs)
#pragma unroll
                for (int hh = 0; hh < 2; hh++)
#pragma unroll
                    for (int g = 0; g < 2; g++) {
                        int n = (hp * 2 + hh) * 2;
                        MMA_BF16(acc[g][n],     ah[g], bh[hh][0], bh[hh][1]);
                        MMA_BF16(acc[g][n + 1], ah[g], bh[hh][2], bh[hh][3]);
                    }
                // pass 2: Al x Bh
#pragma unroll
                for (int hh = 0; hh < 2; hh++)
#pragma unroll
                    for (int g = 0; g < 2; g++) {
                        int n = (hp * 2 + hh) * 2;
                        MMA_BF16(acc[g][n],     al[g], bh[hh][0], bh[hh][1]);
                        MMA_BF16(acc[g][n + 1], al[g], bh[hh][2], bh[hh][3]);
                    }
                // pass 3: Ah x Bl
#pragma unroll
                for (int hh = 0; hh < 2; hh++)
#pragma unroll
                    for (int g = 0; g < 2; g++) {
                        int n = (hp * 2 + hh) * 2;
                        MMA_BF16(acc[g][n],     ah[g], bl[hh][0], bl[hh][1]);
                        MMA_BF16(acc[g][n + 1], ah[g], bl[hh][2], bl[hh][3]);
                    }
            }
        }
        __syncthreads();
    }

    // epilogue: bias add + store
#pragma unroll
    for (int g = 0; g < 2; g++) {
        int row0 = bm + wm * 32 + g * 16 + (lane >> 2);
        int row1 = row0 + 8;
#pragma unroll
        for (int n = 0; n < 8; n++) {
            int col = bn + wn * 64 + n * 8 + (lane & 3) * 2;
            float2 bb = *(const float2*)&bias[col];
            if (row0 < M) {
                float2 o = make_float2(acc[g][n][0] + bb.x, acc[g][n][1] + bb.y);
                *(float2*)&C[(size_t)row0 * N + col] = o;
            }
            if (row1 < M) {
                float2 o = make_float2(acc[g][n][2] + bb.x, acc[g][n][3] + bb.y);
                *(float2*)&C[(size_t)row1 * N + col] = o;
            }
        }
    }
}

// ---------------------------------------------------------------------------
// Launch
// ---------------------------------------------------------------------------
extern "C" void kernel_launch(void* const* d_in, const int* in_sizes, int n_in,
                              void* d_out, int out_size) {
    const float* cf   = (const float*)d_in[0];
    const int* midx   = (const int*)d_in[1];
    const int* seg    = (const int*)d_in[2];
    const float* W    = (const float*)d_in[4];
    const float* bias = (const float*)d_in[5];
    float* out = (float*)d_out;

    const int N = in_sizes[5];           // 512
    const int K = in_sizes[4] / N;       // 256
    const int M = out_size / N;          // 50000
    const int num_members = in_sizes[1]; // 400000
    const int K4 = K / 4;

    cudaFuncSetAttribute(gemm_mma_kernel,
                         cudaFuncAttributeMaxDynamicSharedMemorySize,
                         (int)(NSTAGE * STAGE_BYTES));

    starts_kernel<<<(num_members + 256) / 256, 256>>>(seg, num_members, M);
    prepw_kernel<<<(K * N + 255) / 256, 256>>>(W, K, N);
    mean_kernel<<<M, K4>>>((const float4*)cf, midx, K4);

    dim3 grid((M + 127) / 128, N / 128);
    gemm_mma_kernel<<<grid, 256, NSTAGE * STAGE_BYTES>>>(bias, out, M, N, K);
}

// round 5
// speedup vs baseline: 2.3310x; 1.0945x over previous
#include <cuda_runtime.h>
#include <cuda_bf16.h>
#include <cstdint>

// ---------------------------------------------------------------------------
// out[M,N] = segment_mean(gather(cf, member_idx), segment_ids) @ W + b
// starts[] pass -> mean kernel (emits bf16 hi/lo split A) -> W prepack
// (transpose + hi/lo) -> mma.sync bf16 GEMM, 3-term split, fp32 accumulate.
// R5: __launch_bounds__(256,2) to force regs<=128 -> 2 CTAs/SM (R4 was
//     register-limited to 1 CTA => occ 12.4%, tensor 45%).
// ---------------------------------------------------------------------------

#define MAX_ROWS_PAD 65664          // multiple of 128, >= padded M
#define AK 256                      // K (input_dim) capacity

// Zero-initialized scratch. Rows >= M are never written -> stay zero, so the
// GEMM needs no A-row guards.
__device__ __nv_bfloat16 g_a_hi[(size_t)MAX_ROWS_PAD * AK];
__device__ __nv_bfloat16 g_a_lo[(size_t)MAX_ROWS_PAD * AK];
__device__ __nv_bfloat16 g_b_hi[1024 * 512];   // [N][K] (W transposed)
__device__ __nv_bfloat16 g_b_lo[1024 * 512];
__device__ int g_starts[65600];

// ---------------------------------------------------------------------------
// PTX helpers (baseline sm_80 features — safe through compute_103 PTX)
// ---------------------------------------------------------------------------
__device__ __forceinline__ uint32_t smem_u32(const void* p) {
    uint32_t a;
    asm("{ .reg .u64 t; cvta.to.shared.u64 t, %1; cvt.u32.u64 %0, t; }"
        : "=r"(a) : "l"(p));
    return a;
}

#define CP16(dst, src) \
    asm volatile("cp.async.cg.shared.global [%0], [%1], 16;" \
                 :: "r"(dst), "l"(src) : "memory")
#define CP_COMMIT() asm volatile("cp.async.commit_group;" ::: "memory")
#define CP_WAIT1()  asm volatile("cp.async.wait_group 1;" ::: "memory")

#define LDM4(r, a) \
    asm volatile("ldmatrix.sync.aligned.m8n8.x4.shared.b16 {%0,%1,%2,%3}, [%4];" \
                 : "=r"((r)[0]), "=r"((r)[1]), "=r"((r)[2]), "=r"((r)[3]) \
                 : "r"(a))

#define MMA_BF16(d, a, b0, b1) \
    asm volatile("mma.sync.aligned.m16n8k16.row.col.f32.bf16.bf16.f32 " \
                 "{%0,%1,%2,%3}, {%4,%5,%6,%7}, {%8,%9}, {%0,%1,%2,%3};" \
                 : "+f"((d)[0]), "+f"((d)[1]), "+f"((d)[2]), "+f"((d)[3]) \
                 : "r"((a)[0]), "r"((a)[1]), "r"((a)[2]), "r"((a)[3]), \
                   "r"(b0), "r"(b1))

// ---------------------------------------------------------------------------
// Kernel 0: segment starts
// ---------------------------------------------------------------------------
__global__ void starts_kernel(const int* __restrict__ seg, int num_members, int num_cells) {
    int i = blockIdx.x * blockDim.x + threadIdx.x;
    if (i > num_members) return;
    int cur  = (i < num_members) ? seg[i] : num_cells;
    int prev = (i > 0) ? seg[i - 1] : -1;
    for (int c = prev + 1; c <= cur; c++) g_starts[c] = i;
}

// ---------------------------------------------------------------------------
// Kernel 1: segment mean + bf16 hi/lo split. 128 threads = 2 cells per block
// (64 threads each). Thread t owns float4 chunk t of the 256-dim embedding.
// Index loads are uniform across the half-block (broadcast), no smem/syncs.
// ---------------------------------------------------------------------------
__global__ void mean_kernel(const float4* __restrict__ cf4,
                            const int* __restrict__ midx,
                            int K4, int M) {
    const int c = blockIdx.x * 2 + (threadIdx.x >> 6);
    if (c >= M) return;
    const int tid = threadIdx.x & 63;
    const int start = __ldg(&g_starts[c]);
    const int end   = __ldg(&g_starts[c + 1]);

    float4 a0 = make_float4(0.f, 0.f, 0.f, 0.f);
    float4 a1 = make_float4(0.f, 0.f, 0.f, 0.f);

    int j = start;
    for (; j + 2 <= end; j += 2) {
        int i0 = __ldg(&midx[j])     * K4;
        int i1 = __ldg(&midx[j + 1]) * K4;
        float4 v0 = cf4[(size_t)i0 + tid];
        float4 v1 = cf4[(size_t)i1 + tid];
        a0.x += v0.x; a0.y += v0.y; a0.z += v0.z; a0.w += v0.w;
        a1.x += v1.x; a1.y += v1.y; a1.z += v1.z; a1.w += v1.w;
    }
    if (j < end) {
        int i0 = __ldg(&midx[j]) * K4;
        float4 v0 = cf4[(size_t)i0 + tid];
        a0.x += v0.x; a0.y += v0.y; a0.z += v0.z; a0.w += v0.w;
    }

    float inv = 1.0f / fmaxf((float)(end - start), 1.0f);
    float v[4];
    v[0] = (a0.x + a1.x) * inv;
    v[1] = (a0.y + a1.y) * inv;
    v[2] = (a0.z + a1.z) * inv;
    v[3] = (a0.w + a1.w) * inv;

    uint32_t hp[2], lp[2];
#pragma unroll
    for (int g = 0; g < 2; g++) {
        __nv_bfloat16 h0 = __float2bfloat16(v[2 * g]);
        __nv_bfloat16 h1 = __float2bfloat16(v[2 * g + 1]);
        __nv_bfloat16 l0 = __float2bfloat16(v[2 * g]     - __bfloat162float(h0));
        __nv_bfloat16 l1 = __float2bfloat16(v[2 * g + 1] - __bfloat162float(h1));
        hp[g] = (uint32_t)__bfloat16_as_ushort(h0) | ((uint32_t)__bfloat16_as_ushort(h1) << 16);
        lp[g] = (uint32_t)__bfloat16_as_ushort(l0) | ((uint32_t)__bfloat16_as_ushort(l1) << 16);
    }
    size_t o = (size_t)c * K4 + tid;   // uint2 units (4 bf16 = 8B)
    ((uint2*)g_a_hi)[o] = make_uint2(hp[0], hp[1]);
    ((uint2*)g_a_lo)[o] = make_uint2(lp[0], lp[1]);
}

// ---------------------------------------------------------------------------
// Kernel 2: W prepack -> [N][K] bf16 hi/lo
// ---------------------------------------------------------------------------
__global__ void prepw_kernel(const float* __restrict__ W, int K, int N) {
    int idx = blockIdx.x * blockDim.x + threadIdx.x;
    if (idx >= K * N) return;
    int n = idx / K, k = idx - n * K;
    float w = W[(size_t)k * N + n];
    __nv_bfloat16 h = __float2bfloat16(w);
    __nv_bfloat16 l = __float2bfloat16(w - __bfloat162float(h));
    g_b_hi[(size_t)n * K + k] = h;
    g_b_lo[(size_t)n * K + k] = l;
}

// ---------------------------------------------------------------------------
// Kernel 3: bf16 mma.sync GEMM, 3-term split, 3-stage cp.async pipeline.
// CTA tile 128x128, BK=32, 256 thr = 8 warps (4 M x 2 N), warp tile 32x64.
// Smem rows 64B (32 bf16), XOR-swizzled 16B chunks for conflict-free ldmatrix.
// Stage layout: Ah[8K] Al[8K] Bh[8K] Bl[8K] = 32KB; 3 stages = 96KB.
// __launch_bounds__(256, 2): cap regs at 128 so 2 CTAs fit per SM.
// ---------------------------------------------------------------------------
#define STAGE_BYTES 32768u
#define SEC_BYTES   8192u
#define NSTAGE      3

__global__ __launch_bounds__(256, 2)
void gemm_mma_kernel(const float* __restrict__ bias, float* __restrict__ C,
                     int M, int N, int K) {
    extern __shared__ char smem[];
    const uint32_t sb = smem_u32(smem);
    const int tid  = threadIdx.x;
    const int wid  = tid >> 5, lane = tid & 31;
    const int wm   = wid & 3;            // warp row (0..3) -> 32 rows
    const int wn   = wid >> 2;           // warp col (0..1) -> 64 cols
    const int bm   = blockIdx.x * 128, bn = blockIdx.y * 128;
    const size_t rowb = (size_t)K * 2;   // bytes per gmem row

    const char* pAh = (const char*)g_a_hi + (size_t)bm * rowb;
    const char* pAl = (const char*)g_a_lo + (size_t)bm * rowb;
    const char* pBh = (const char*)g_b_hi + (size_t)bn * rowb;
    const char* pBl = (const char*)g_b_lo + (size_t)bn * rowb;

    // this thread's two (row, chunk) load slots per section
    const int li0 = tid * 2, li1 = tid * 2 + 1;
    const int lr0 = li0 >> 2, lc0 = li0 & 3;
    const int lr1 = li1 >> 2, lc1 = li1 & 3;
    const uint32_t ld0 = (uint32_t)(lr0 * 64 + (((lc0 ^ ((lr0 >> 1) & 3))) << 4));
    const uint32_t ld1 = (uint32_t)(lr1 * 64 + (((lc1 ^ ((lr1 >> 1) & 3))) << 4));

    float acc[2][8][4];
#pragma unroll
    for (int g = 0; g < 2; g++)
#pragma unroll
        for (int n = 0; n < 8; n++)
#pragma unroll
            for (int j = 0; j < 4; j++) acc[g][n][j] = 0.f;

    // ldmatrix lane addressing
    const int a_r = (lane & 15);
    const int a_cadd = (lane >> 4);
    const int b_r = (lane & 7) + ((lane >> 4) << 3);
    const int b_cadd = ((lane >> 3) & 1);

    const int nit = K >> 5;              // 8 for K=256

    // prologue: load stages 0 and 1
#pragma unroll
    for (int pre = 0; pre < 2; pre++) {
        const uint32_t sbase = sb + (uint32_t)pre * STAGE_BYTES;
        const size_t kt2 = (size_t)pre * 64;
#pragma unroll
        for (int s = 0; s < 4; s++) {
            const char* gp = (s == 0) ? pAh : (s == 1) ? pAl : (s == 2) ? pBh : pBl;
            CP16(sbase + s * SEC_BYTES + ld0, gp + (size_t)lr0 * rowb + kt2 + lc0 * 16);
            CP16(sbase + s * SEC_BYTES + ld1, gp + (size_t)lr1 * rowb + kt2 + lc1 * 16);
        }
        CP_COMMIT();
    }

    for (int it = 0; it < nit; it++) {
        const uint32_t stg = sb + (uint32_t)(it % NSTAGE) * STAGE_BYTES;
        CP_WAIT1();              // stage `it` complete (1 newer group may fly)
        __syncthreads();         // all warps done with stage it-1's compute

        if (it + 2 < nit) {      // prefetch stage it+2 into slot (it+2)%3
            const uint32_t sbase = sb + (uint32_t)((it + 2) % NSTAGE) * STAGE_BYTES;
            const size_t kt2 = (size_t)(it + 2) * 64;
#pragma unroll
            for (int s = 0; s < 4; s++) {
                const char* gp = (s == 0) ? pAh : (s == 1) ? pAl : (s == 2) ? pBh : pBl;
                CP16(sbase + s * SEC_BYTES + ld0, gp + (size_t)lr0 * rowb + kt2 + lc0 * 16);
                CP16(sbase + s * SEC_BYTES + ld1, gp + (size_t)lr1 * rowb + kt2 + lc1 * 16);
            }
            CP_COMMIT();
        } else {
            CP_COMMIT();         // keep group count in lockstep for WAIT1
        }

        // compute: two k16 steps on this stage
#pragma unroll
        for (int s = 0; s < 2; s++) {
            uint32_t ah[2][4], al[2][4];
#pragma unroll
            for (int g = 0; g < 2; g++) {
                int row = wm * 32 + g * 16 + a_r;
                int ch  = s * 2 + a_cadd;
                uint32_t addr = stg + row * 64 + (((ch ^ ((row >> 1) & 3))) << 4);
                LDM4(ah[g], addr);
                LDM4(al[g], addr + SEC_BYTES);
            }
#pragma unroll
            for (int hp = 0; hp < 2; hp++) {
                uint32_t bh[2][4], bl[2][4];
#pragma unroll
                for (int hh = 0; hh < 2; hh++) {
                    int h = hp * 2 + hh;
                    int row = wn * 64 + h * 16 + b_r;
                    int ch  = s * 2 + b_cadd;
                    uint32_t addr = stg + 2 * SEC_BYTES + row * 64 +
                                    (((ch ^ ((row >> 1) & 3))) << 4);
                    LDM4(bh[hh], addr);
                    LDM4(bl[hh], addr + SEC_BYTES);
                }
                // pass 1: Ah x Bh  (8 independent MMAs)
#pragma unroll
                for (int hh = 0; hh < 2; hh++)
#pragma unroll
                    for (int g = 0; g < 2; g++) {
                        int n = (hp * 2 + hh) * 2;
                        MMA_BF16(acc[g][n],     ah[g], bh[hh][0], bh[hh][1]);
                        MMA_BF16(acc[g][n + 1], ah[g], bh[hh][2], bh[hh][3]);
                    }
                // pass 2: Al x Bh
#pragma unroll
                for (int hh = 0; hh < 2; hh++)
#pragma unroll
                    for (int g = 0; g < 2; g++) {
                        int n = (hp * 2 + hh) * 2;
                        MMA_BF16(acc[g][n],     al[g], bh[hh][0], bh[hh][1]);
                        MMA_BF16(acc[g][n + 1], al[g], bh[hh][2], bh[hh][3]);
                    }
                // pass 3: Ah x Bl
#pragma unroll
                for (int hh = 0; hh < 2; hh++)
#pragma unroll
                    for (int g = 0; g < 2; g++) {
                        int n = (hp * 2 + hh) * 2;
                        MMA_BF16(acc[g][n],     ah[g], bl[hh][0], bl[hh][1]);
                        MMA_BF16(acc[g][n + 1], ah[g], bl[hh][2], bl[hh][3]);
                    }
            }
        }
        __syncthreads();
    }

    // epilogue: bias add + store
#pragma unroll
    for (int g = 0; g < 2; g++) {
        int row0 = bm + wm * 32 + g * 16 + (lane >> 2);
        int row1 = row0 + 8;
#pragma unroll
        for (int n = 0; n < 8; n++) {
            int col = bn + wn * 64 + n * 8 + (lane & 3) * 2;
            float2 bb = *(const float2*)&bias[col];
            if (row0 < M) {
                float2 o = make_float2(acc[g][n][0] + bb.x, acc[g][n][1] + bb.y);
                *(float2*)&C[(size_t)row0 * N + col] = o;
            }
            if (row1 < M) {
                float2 o = make_float2(acc[g][n][2] + bb.x, acc[g][n][3] + bb.y);
                *(float2*)&C[(size_t)row1 * N + col] = o;
            }
        }
    }
}

// ---------------------------------------------------------------------------
// Launch
// ---------------------------------------------------------------------------
extern "C" void kernel_launch(void* const* d_in, const int* in_sizes, int n_in,
                              void* d_out, int out_size) {
    const float* cf   = (const float*)d_in[0];
    const int* midx   = (const int*)d_in[1];
    const int* seg    = (const int*)d_in[2];
    const float* W    = (const float*)d_in[4];
    const float* bias = (const float*)d_in[5];
    float* out = (float*)d_out;

    const int N = in_sizes[5];           // 512
    const int K = in_sizes[4] / N;       // 256
    const int M = out_size / N;          // 50000
    const int num_members = in_sizes[1]; // 400000
    const int K4 = K / 4;

    cudaFuncSetAttribute(gemm_mma_kernel,
                         cudaFuncAttributeMaxDynamicSharedMemorySize,
                         (int)(NSTAGE * STAGE_BYTES));

    starts_kernel<<<(num_members + 256) / 256, 256>>>(seg, num_members, M);
    prepw_kernel<<<(K * N + 255) / 256, 256>>>(W, K, N);
    mean_kernel<<<(M + 1) / 2, 128>>>((const float4*)cf, midx, K4, M);

    dim3 grid((M + 127) / 128, N / 128);
    gemm_mma_kernel<<<grid, 256, NSTAGE * STAGE_BYTES>>>(bias, out, M, N, K);
}

// round 6
// speedup vs baseline: 3.8736x; 1.6618x over previous
#include <cuda_runtime.h>
#include <cuda_fp16.h>
#include <cstdint>

// ---------------------------------------------------------------------------
// out[M,N] = segment_mean(gather(cf, member_idx), segment_ids) @ W + b
// starts[] pass -> mean kernel (emits fp16 A) -> W prepack (transpose, fp16)
// -> single-term fp16 mma.sync GEMM (fp32 accumulate).
// R6: fp16 (11-bit mantissa) needs NO hi/lo split for rel_err < 1e-3
//     (predicted ~4e-4). 1/3 the MMAs, 1/2 the traffic vs R5. BK=64 stages.
// ---------------------------------------------------------------------------

#define MAX_ROWS_PAD 65664          // multiple of 128, >= padded M
#define AK 256                      // K (input_dim) capacity

// Zero-initialized scratch. Rows >= M never written -> stay zero (no guards).
__device__ __half g_a[(size_t)MAX_ROWS_PAD * AK];
__device__ __half g_b[1024 * 512];          // [N][K] (W transposed)
__device__ int g_starts[65600];

// ---------------------------------------------------------------------------
// PTX helpers (baseline sm_80 features — safe through compute_103 PTX)
// ---------------------------------------------------------------------------
__device__ __forceinline__ uint32_t smem_u32(const void* p) {
    uint32_t a;
    asm("{ .reg .u64 t; cvta.to.shared.u64 t, %1; cvt.u32.u64 %0, t; }"
        : "=r"(a) : "l"(p));
    return a;
}

#define CP16(dst, src) \
    asm volatile("cp.async.cg.shared.global [%0], [%1], 16;" \
                 :: "r"(dst), "l"(src) : "memory")
#define CP_COMMIT() asm volatile("cp.async.commit_group;" ::: "memory")
#define CP_WAIT1()  asm volatile("cp.async.wait_group 1;" ::: "memory")

#define LDM4(r, a) \
    asm volatile("ldmatrix.sync.aligned.m8n8.x4.shared.b16 {%0,%1,%2,%3}, [%4];" \
                 : "=r"((r)[0]), "=r"((r)[1]), "=r"((r)[2]), "=r"((r)[3]) \
                 : "r"(a))

#define MMA_F16(d, a, b0, b1) \
    asm volatile("mma.sync.aligned.m16n8k16.row.col.f32.f16.f16.f32 " \
                 "{%0,%1,%2,%3}, {%4,%5,%6,%7}, {%8,%9}, {%0,%1,%2,%3};" \
                 : "+f"((d)[0]), "+f"((d)[1]), "+f"((d)[2]), "+f"((d)[3]) \
                 : "r"((a)[0]), "r"((a)[1]), "r"((a)[2]), "r"((a)[3]), \
                   "r"(b0), "r"(b1))

// ---------------------------------------------------------------------------
// Kernel 0: segment starts
// ---------------------------------------------------------------------------
__global__ void starts_kernel(const int* __restrict__ seg, int num_members, int num_cells) {
    int i = blockIdx.x * blockDim.x + threadIdx.x;
    if (i > num_members) return;
    int cur  = (i < num_members) ? seg[i] : num_cells;
    int prev = (i > 0) ? seg[i - 1] : -1;
    for (int c = prev + 1; c <= cur; c++) g_starts[c] = i;
}

// ---------------------------------------------------------------------------
// Kernel 1: segment mean -> fp16. 128 threads = 2 cells per block (64 each).
// Thread t owns float4 chunk t. Index loads are uniform broadcasts.
// ---------------------------------------------------------------------------
__global__ void mean_kernel(const float4* __restrict__ cf4,
                            const int* __restrict__ midx,
                            int K4, int M) {
    const int c = blockIdx.x * 2 + (threadIdx.x >> 6);
    if (c >= M) return;
    const int tid = threadIdx.x & 63;
    const int start = __ldg(&g_starts[c]);
    const int end   = __ldg(&g_starts[c + 1]);

    float4 a0 = make_float4(0.f, 0.f, 0.f, 0.f);
    float4 a1 = make_float4(0.f, 0.f, 0.f, 0.f);

    int j = start;
    for (; j + 2 <= end; j += 2) {
        int i0 = __ldg(&midx[j])     * K4;
        int i1 = __ldg(&midx[j + 1]) * K4;
        float4 v0 = cf4[(size_t)i0 + tid];
        float4 v1 = cf4[(size_t)i1 + tid];
        a0.x += v0.x; a0.y += v0.y; a0.z += v0.z; a0.w += v0.w;
        a1.x += v1.x; a1.y += v1.y; a1.z += v1.z; a1.w += v1.w;
    }
    if (j < end) {
        int i0 = __ldg(&midx[j]) * K4;
        float4 v0 = cf4[(size_t)i0 + tid];
        a0.x += v0.x; a0.y += v0.y; a0.z += v0.z; a0.w += v0.w;
    }

    float inv = 1.0f / fmaxf((float)(end - start), 1.0f);
    __half2 h0 = __floats2half2_rn((a0.x + a1.x) * inv, (a0.y + a1.y) * inv);
    __half2 h1 = __floats2half2_rn((a0.z + a1.z) * inv, (a0.w + a1.w) * inv);
    uint2 pk;
    pk.x = *(uint32_t*)&h0;
    pk.y = *(uint32_t*)&h1;
    ((uint2*)g_a)[(size_t)c * K4 + tid] = pk;
}

// ---------------------------------------------------------------------------
// Kernel 2: W prepack -> [N][K] fp16 (transposed for mma.sync col-major B)
// ---------------------------------------------------------------------------
__global__ void prepw_kernel(const float* __restrict__ W, int K, int N) {
    int idx = blockIdx.x * blockDim.x + threadIdx.x;
    if (idx >= K * N) return;
    int n = idx / K, k = idx - n * K;
    g_b[(size_t)n * K + k] = __float2half_rn(W[(size_t)k * N + n]);
}

// ---------------------------------------------------------------------------
// Kernel 3: fp16 mma.sync GEMM, single term, 3-stage cp.async pipeline.
// CTA tile 128x128, BK=64, 256 thr = 8 warps (4M x 2N), warp tile 32x64.
// Smem rows 128B (64 fp16), SW128 swizzle: chunk ch -> ch ^ (row&7).
// Stage: A[16KB] B[16KB] = 32KB; 3 stages = 96KB; 2 CTAs/SM = 192KB <= 228.
// ---------------------------------------------------------------------------
#define STAGE_BYTES 32768u
#define SEC_BYTES   16384u
#define NSTAGE      3

__global__ __launch_bounds__(256, 2)
void gemm_mma_kernel(const float* __restrict__ bias, float* __restrict__ C,
                     int M, int N, int K) {
    extern __shared__ char smem[];
    const uint32_t sb = smem_u32(smem);
    const int tid  = threadIdx.x;
    const int wid  = tid >> 5, lane = tid & 31;
    const int wm   = wid & 3;            // warp row (0..3) -> 32 rows
    const int wn   = wid >> 2;           // warp col (0..1) -> 64 cols
    const int bm   = blockIdx.x * 128, bn = blockIdx.y * 128;
    const size_t rowb = (size_t)K * 2;   // bytes per gmem row

    const char* pA = (const char*)g_a + (size_t)bm * rowb;
    const char* pB = (const char*)g_b + (size_t)bn * rowb;

    // loader: 4 chunks (16B) per section per thread; 1024 chunks per section
    // idx = i*256 + tid; r = idx>>3 (row 0..127), ch = idx&7 (chunk in row)
    uint32_t sdst[4];   // swizzled smem offsets (stage-relative)
    int lrow[4], lch[4];
#pragma unroll
    for (int i = 0; i < 4; i++) {
        int idx = i * 256 + tid;
        lrow[i] = idx >> 3;
        lch[i]  = idx & 7;
        sdst[i] = (uint32_t)(lrow[i] * 128 + ((lch[i] ^ (lrow[i] & 7)) << 4));
    }

    float acc[2][8][4];
#pragma unroll
    for (int g = 0; g < 2; g++)
#pragma unroll
        for (int n = 0; n < 8; n++)
#pragma unroll
            for (int j = 0; j < 4; j++) acc[g][n][j] = 0.f;

    // ldmatrix lane addressing
    const int a_r = (lane & 15);
    const int a_cadd = (lane >> 4);           // 0/1
    const int b_r = (lane & 7) + ((lane >> 4) << 3);
    const int b_cadd = ((lane >> 3) & 1);     // 0/1

    const int nit = K >> 6;              // 4 for K=256

    // prologue: stages 0 and 1
#pragma unroll
    for (int pre = 0; pre < 2; pre++) {
        const uint32_t sbase = sb + (uint32_t)pre * STAGE_BYTES;
        const size_t kt = (size_t)pre * 128;  // 64 fp16 = 128 B per stage
#pragma unroll
        for (int i = 0; i < 4; i++) {
            CP16(sbase + sdst[i],             pA + (size_t)lrow[i] * rowb + kt + lch[i] * 16);
            CP16(sbase + SEC_BYTES + sdst[i], pB + (size_t)lrow[i] * rowb + kt + lch[i] * 16);
        }
        CP_COMMIT();
    }

    for (int it = 0; it < nit; it++) {
        const uint32_t stg = sb + (uint32_t)(it % NSTAGE) * STAGE_BYTES;
        CP_WAIT1();              // stage `it` complete
        __syncthreads();

        if (it + 2 < nit) {
            const uint32_t sbase = sb + (uint32_t)((it + 2) % NSTAGE) * STAGE_BYTES;
            const size_t kt = (size_t)(it + 2) * 128;
#pragma unroll
            for (int i = 0; i < 4; i++) {
                CP16(sbase + sdst[i],             pA + (size_t)lrow[i] * rowb + kt + lch[i] * 16);
                CP16(sbase + SEC_BYTES + sdst[i], pB + (size_t)lrow[i] * rowb + kt + lch[i] * 16);
            }
            CP_COMMIT();
        } else {
            CP_COMMIT();         // keep group count in lockstep for WAIT1
        }

        // compute: four k16 steps on this stage
#pragma unroll
        for (int s = 0; s < 4; s++) {
            uint32_t af[2][4];
#pragma unroll
            for (int g = 0; g < 2; g++) {
                int row = wm * 32 + g * 16 + a_r;
                int ch  = s * 2 + a_cadd;
                LDM4(af[g], stg + row * 128 + ((ch ^ (row & 7)) << 4));
            }
            uint32_t bf[4][4];
#pragma unroll
            for (int h = 0; h < 4; h++) {
                int row = wn * 64 + h * 16 + b_r;
                int ch  = s * 2 + b_cadd;
                LDM4(bf[h], stg + SEC_BYTES + row * 128 + ((ch ^ (row & 7)) << 4));
            }
            // 16 independent MMAs (each acc written once per s)
#pragma unroll
            for (int h = 0; h < 4; h++)
#pragma unroll
                for (int g = 0; g < 2; g++) {
                    MMA_F16(acc[g][h * 2],     af[g], bf[h][0], bf[h][1]);
                    MMA_F16(acc[g][h * 2 + 1], af[g], bf[h][2], bf[h][3]);
                }
        }
        __syncthreads();
    }

    // epilogue: bias add + store
#pragma unroll
    for (int g = 0; g < 2; g++) {
        int row0 = bm + wm * 32 + g * 16 + (lane >> 2);
        int row1 = row0 + 8;
#pragma unroll
        for (int n = 0; n < 8; n++) {
            int col = bn + wn * 64 + n * 8 + (lane & 3) * 2;
            float2 bb = *(const float2*)&bias[col];
            if (row0 < M) {
                float2 o = make_float2(acc[g][n][0] + bb.x, acc[g][n][1] + bb.y);
                *(float2*)&C[(size_t)row0 * N + col] = o;
            }
            if (row1 < M) {
                float2 o = make_float2(acc[g][n][2] + bb.x, acc[g][n][3] + bb.y);
                *(float2*)&C[(size_t)row1 * N + col] = o;
            }
        }
    }
}

// ---------------------------------------------------------------------------
// Launch
// ---------------------------------------------------------------------------
extern "C" void kernel_launch(void* const* d_in, const int* in_sizes, int n_in,
                              void* d_out, int out_size) {
    const float* cf   = (const float*)d_in[0];
    const int* midx   = (const int*)d_in[1];
    const int* seg    = (const int*)d_in[2];
    const float* W    = (const float*)d_in[4];
    const float* bias = (const float*)d_in[5];
    float* out = (float*)d_out;

    const int N = in_sizes[5];           // 512
    const int K = in_sizes[4] / N;       // 256
    const int M = out_size / N;          // 50000
    const int num_members = in_sizes[1]; // 400000
    const int K4 = K / 4;

    cudaFuncSetAttribute(gemm_mma_kernel,
                         cudaFuncAttributeMaxDynamicSharedMemorySize,
                         (int)(NSTAGE * STAGE_BYTES));

    starts_kernel<<<(num_members + 256) / 256, 256>>>(seg, num_members, M);
    prepw_kernel<<<(K * N + 255) / 256, 256>>>(W, K, N);
    mean_kernel<<<(M + 1) / 2, 128>>>((const float4*)cf, midx, K4, M);

    dim3 grid((M + 127) / 128, N / 128);
    gemm_mma_kernel<<<grid, 256, NSTAGE * STAGE_BYTES>>>(bias, out, M, N, K);
}